// round 1
// baseline (speedup 1.0000x reference)
#include <cuda_runtime.h>

#define T_SEQ  2048
#define NB     4
#define NH     12
#define DH     64
#define DMODEL 768

// Scratch (device globals — no runtime allocation allowed)
__device__ float g_q[NB * NH * T_SEQ * DH];
__device__ float g_k[NB * NH * T_SEQ * DH];
__device__ float g_v[NB * NH * T_SEQ * DH];
__device__ float g_attn[NB * T_SEQ * DMODEL];

// ---------------------------------------------------------------------------
// QKV GEMM: out[m,n] = sum_k X[m,k] * W[n,k] + bias[n]
// M = 8192 (B*T), N = 2304 (3*D), K = 768
// 64x64 block tile, BK=16, 128 threads, 4x8 register micro-tile.
// Epilogue scatters into g_q/g_k/g_v with [B,H,T,Dh] layout.
// ---------------------------------------------------------------------------
__global__ void __launch_bounds__(128) qkv_gemm_kernel(
    const float* __restrict__ X, const float* __restrict__ W,
    const float* __restrict__ bias)
{
    __shared__ float As[64][17];
    __shared__ float Bs[64][17];
    const int K = DMODEL;
    const int tid = threadIdx.x;
    const int bn = blockIdx.x, bm = blockIdx.y;
    const int tx = tid & 7, ty = tid >> 3;
    const int m0 = ty * 4, n0 = tx * 8;

    float acc[4][8];
#pragma unroll
    for (int i = 0; i < 4; i++)
#pragma unroll
        for (int j = 0; j < 8; j++) acc[i][j] = 0.f;

    const float* Abase = X + (size_t)bm * 64 * K;
    const float* Bbase = W + (size_t)bn * 64 * K;

    for (int kt = 0; kt < K; kt += 16) {
#pragma unroll
        for (int it = 0; it < 2; it++) {
            int e = tid + it * 128;
            int r = e >> 2, c = (e & 3) << 2;
            float4 va = *(const float4*)(Abase + (size_t)r * K + kt + c);
            As[r][c] = va.x; As[r][c + 1] = va.y; As[r][c + 2] = va.z; As[r][c + 3] = va.w;
            float4 vb = *(const float4*)(Bbase + (size_t)r * K + kt + c);
            Bs[r][c] = vb.x; Bs[r][c + 1] = vb.y; Bs[r][c + 2] = vb.z; Bs[r][c + 3] = vb.w;
        }
        __syncthreads();
#pragma unroll
        for (int kk = 0; kk < 16; kk++) {
            float a[4], b[8];
#pragma unroll
            for (int i = 0; i < 4; i++) a[i] = As[m0 + i][kk];
#pragma unroll
            for (int j = 0; j < 8; j++) b[j] = Bs[n0 + j][kk];
#pragma unroll
            for (int i = 0; i < 4; i++)
#pragma unroll
                for (int j = 0; j < 8; j++)
                    acc[i][j] = fmaf(a[i], b[j], acc[i][j]);
        }
        __syncthreads();
    }

    // Scatter epilogue: column tile (64-wide, 64-aligned) lies within exactly
    // one (which, head) pair since 768 % 64 == 0.
    const int nbase = bn * 64;
    const int which = nbase / DMODEL;
    const int hh = (nbase % DMODEL) / DH;
    float* dst = (which == 0) ? g_q : (which == 1) ? g_k : g_v;
#pragma unroll
    for (int i = 0; i < 4; i++) {
        int m = bm * 64 + m0 + i;
        int b = m >> 11;              // / T_SEQ
        int t = m & (T_SEQ - 1);
        float* drow = dst + (((size_t)(b * NH + hh)) * T_SEQ + t) * DH;
#pragma unroll
        for (int j = 0; j < 8; j++) {
            int d = n0 + j;
            drow[d] = acc[i][j] + bias[nbase + d];
        }
    }
}

// ---------------------------------------------------------------------------
// Flash attention: one block per (q-tile of 64 rows, head, batch).
// 128 threads. Online softmax, fp32. Output written in [B,T,H*Dh] layout.
// Dynamic smem: Qs,Ks,Vs,Ss each 64x65 floats = 66560 bytes total.
// ---------------------------------------------------------------------------
extern __shared__ float s_attn[];

__global__ void __launch_bounds__(128) attn_kernel(float* __restrict__ out)
{
    float (*Qs)[65] = (float(*)[65])(s_attn);
    float (*Ks)[65] = (float(*)[65])(s_attn + 64 * 65);
    float (*Vs)[65] = (float(*)[65])(s_attn + 2 * 64 * 65);
    float (*Ss)[65] = (float(*)[65])(s_attn + 3 * 64 * 65);

    const int tid = threadIdx.x;
    const int qt = blockIdx.x, h = blockIdx.y, b = blockIdx.z;
    const int tx = tid & 7, ty = tid >> 3;
    const int m0 = ty * 4, d0 = tx * 8;

    const size_t bh = ((size_t)(b * NH + h)) * T_SEQ * DH;
    const float* Qg = g_q + bh + (size_t)qt * 64 * DH;
    const float* Kg = g_k + bh;
    const float* Vg = g_v + bh;
    const float scale = 0.125f;  // 1/sqrt(64)

    // Load + pre-scale Q tile
#pragma unroll
    for (int it = 0; it < 8; it++) {
        int e = tid + it * 128;
        int r = e >> 4, c = (e & 15) << 2;
        float4 v = *(const float4*)(Qg + r * DH + c);
        Qs[r][c] = v.x * scale; Qs[r][c + 1] = v.y * scale;
        Qs[r][c + 2] = v.z * scale; Qs[r][c + 3] = v.w * scale;
    }

    float m_i[4], l_i[4], O[4][8];
#pragma unroll
    for (int i = 0; i < 4; i++) {
        m_i[i] = -1e30f;
        l_i[i] = 0.f;
#pragma unroll
        for (int j = 0; j < 8; j++) O[i][j] = 0.f;
    }

    for (int kt = 0; kt < T_SEQ; kt += 64) {
        __syncthreads();  // protect Ks/Vs from readers of previous tile
#pragma unroll
        for (int it = 0; it < 8; it++) {
            int e = tid + it * 128;
            int r = e >> 4, c = (e & 15) << 2;
            float4 kv = *(const float4*)(Kg + (size_t)(kt + r) * DH + c);
            Ks[r][c] = kv.x; Ks[r][c + 1] = kv.y; Ks[r][c + 2] = kv.z; Ks[r][c + 3] = kv.w;
            float4 vv = *(const float4*)(Vg + (size_t)(kt + r) * DH + c);
            Vs[r][c] = vv.x; Vs[r][c + 1] = vv.y; Vs[r][c + 2] = vv.z; Vs[r][c + 3] = vv.w;
        }
        __syncthreads();

        // S = (Q*scale) K^T  (4x8 per thread)
        float acc[4][8];
#pragma unroll
        for (int i = 0; i < 4; i++)
#pragma unroll
            for (int j = 0; j < 8; j++) acc[i][j] = 0.f;
#pragma unroll 16
        for (int d = 0; d < DH; d++) {
            float a[4], kb[8];
#pragma unroll
            for (int i = 0; i < 4; i++) a[i] = Qs[m0 + i][d];
#pragma unroll
            for (int j = 0; j < 8; j++) kb[j] = Ks[d0 + j][d];
#pragma unroll
            for (int i = 0; i < 4; i++)
#pragma unroll
                for (int j = 0; j < 8; j++)
                    acc[i][j] = fmaf(a[i], kb[j], acc[i][j]);
        }

        // Online softmax: row stats replicated across the 8-lane tx group
#pragma unroll
        for (int i = 0; i < 4; i++) {
            float rmax = acc[i][0];
#pragma unroll
            for (int j = 1; j < 8; j++) rmax = fmaxf(rmax, acc[i][j]);
#pragma unroll
            for (int off = 1; off < 8; off <<= 1)
                rmax = fmaxf(rmax, __shfl_xor_sync(0xffffffffu, rmax, off));
            float mnew = fmaxf(m_i[i], rmax);
            float corr = __expf(m_i[i] - mnew);
            float rsum = 0.f;
#pragma unroll
            for (int j = 0; j < 8; j++) {
                acc[i][j] = __expf(acc[i][j] - mnew);
                rsum += acc[i][j];
            }
#pragma unroll
            for (int off = 1; off < 8; off <<= 1)
                rsum += __shfl_xor_sync(0xffffffffu, rsum, off);
            l_i[i] = l_i[i] * corr + rsum;
            m_i[i] = mnew;
#pragma unroll
            for (int j = 0; j < 8; j++) O[i][j] *= corr;
#pragma unroll
            for (int j = 0; j < 8; j++) Ss[m0 + i][d0 + j] = acc[i][j];
        }
        __syncwarp();  // Ss rows are produced/consumed within one warp

        // O += P @ V
#pragma unroll 16
        for (int n = 0; n < 64; n++) {
            float p[4], vv[8];
#pragma unroll
            for (int i = 0; i < 4; i++) p[i] = Ss[m0 + i][n];
#pragma unroll
            for (int j = 0; j < 8; j++) vv[j] = Vs[n][d0 + j];
#pragma unroll
            for (int i = 0; i < 4; i++)
#pragma unroll
                for (int j = 0; j < 8; j++)
                    O[i][j] = fmaf(p[i], vv[j], O[i][j]);
        }
    }

    // Normalize and write [B,T,H*Dh]
#pragma unroll
    for (int i = 0; i < 4; i++) {
        float inv = 1.f / l_i[i];
        int t = qt * 64 + m0 + i;
        float* drow = out + ((size_t)b * T_SEQ + t) * DMODEL + h * DH;
#pragma unroll
        for (int j = 0; j < 8; j++)
            drow[d0 + j] = O[i][j] * inv;
    }
}

// ---------------------------------------------------------------------------
// Projection GEMM: out[m,n] = sum_k A[m,k] * W[n,k] + bias[n]
// M = 8192, N = K = 768
// ---------------------------------------------------------------------------
__global__ void __launch_bounds__(128) proj_gemm_kernel(
    const float* __restrict__ A, const float* __restrict__ W,
    const float* __restrict__ bias, float* __restrict__ out)
{
    __shared__ float As[64][17];
    __shared__ float Bs[64][17];
    const int K = DMODEL;
    const int tid = threadIdx.x;
    const int bn = blockIdx.x, bm = blockIdx.y;
    const int tx = tid & 7, ty = tid >> 3;
    const int m0 = ty * 4, n0 = tx * 8;

    float acc[4][8];
#pragma unroll
    for (int i = 0; i < 4; i++)
#pragma unroll
        for (int j = 0; j < 8; j++) acc[i][j] = 0.f;

    const float* Abase = A + (size_t)bm * 64 * K;
    const float* Bbase = W + (size_t)bn * 64 * K;

    for (int kt = 0; kt < K; kt += 16) {
#pragma unroll
        for (int it = 0; it < 2; it++) {
            int e = tid + it * 128;
            int r = e >> 2, c = (e & 3) << 2;
            float4 va = *(const float4*)(Abase + (size_t)r * K + kt + c);
            As[r][c] = va.x; As[r][c + 1] = va.y; As[r][c + 2] = va.z; As[r][c + 3] = va.w;
            float4 vb = *(const float4*)(Bbase + (size_t)r * K + kt + c);
            Bs[r][c] = vb.x; Bs[r][c + 1] = vb.y; Bs[r][c + 2] = vb.z; Bs[r][c + 3] = vb.w;
        }
        __syncthreads();
#pragma unroll
        for (int kk = 0; kk < 16; kk++) {
            float a[4], b[8];
#pragma unroll
            for (int i = 0; i < 4; i++) a[i] = As[m0 + i][kk];
#pragma unroll
            for (int j = 0; j < 8; j++) b[j] = Bs[n0 + j][kk];
#pragma unroll
            for (int i = 0; i < 4; i++)
#pragma unroll
                for (int j = 0; j < 8; j++)
                    acc[i][j] = fmaf(a[i], b[j], acc[i][j]);
        }
        __syncthreads();
    }

    const int nbase = bn * 64;
#pragma unroll
    for (int i = 0; i < 4; i++) {
        int m = bm * 64 + m0 + i;
        float* drow = out + (size_t)m * DMODEL;
#pragma unroll
        for (int j = 0; j < 8; j++) {
            int n = nbase + n0 + j;
            drow[n] = acc[i][j] + bias[n];
        }
    }
}

// ---------------------------------------------------------------------------
extern "C" void kernel_launch(void* const* d_in, const int* in_sizes, int n_in,
                              void* d_out, int out_size)
{
    const float* x      = (const float*)d_in[0];
    const float* W_qkv  = (const float*)d_in[1];
    const float* b_qkv  = (const float*)d_in[2];
    const float* W_proj = (const float*)d_in[3];
    const float* b_proj = (const float*)d_in[4];
    float* out = (float*)d_out;

    const int ATTN_SMEM = 4 * 64 * 65 * (int)sizeof(float);  // 66560 B
    cudaFuncSetAttribute(attn_kernel,
                         cudaFuncAttributeMaxDynamicSharedMemorySize, ATTN_SMEM);

    float* attn_scratch;
    cudaGetSymbolAddress((void**)&attn_scratch, g_attn);

    // 1) QKV GEMM + scatter to per-head Q/K/V
    {
        dim3 grid(3 * DMODEL / 64, (NB * T_SEQ) / 64);  // (36, 128)
        qkv_gemm_kernel<<<grid, 128>>>(x, W_qkv, b_qkv);
    }
    // 2) Flash attention
    {
        dim3 grid(T_SEQ / 64, NH, NB);  // (32, 12, 4)
        attn_kernel<<<grid, 128, ATTN_SMEM>>>(attn_scratch);
    }
    // 3) Output projection
    {
        dim3 grid(DMODEL / 64, (NB * T_SEQ) / 64);  // (12, 128)
        proj_gemm_kernel<<<grid, 128>>>(attn_scratch, W_proj, b_proj, out);
    }
}

// round 2
// speedup vs baseline: 1.5974x; 1.5974x over previous
#include <cuda_runtime.h>
#include <mma.h>
using namespace nvcuda;

#define T_SEQ  2048
#define NB     4
#define NH     12
#define DH     64
#define DMODEL 768

// Scratch (device globals — no runtime allocation allowed)
__device__ float g_q[NB * NH * T_SEQ * DH];
__device__ float g_k[NB * NH * T_SEQ * DH];
__device__ float g_v[NB * NH * T_SEQ * DH];
__device__ float g_attn[NB * T_SEQ * DMODEL];

// ---------------------------------------------------------------------------
// tf32 wmma GEMM: out[m,n] = sum_k A[m,k] * W[n,k] + bias[n]
// Block tile 128(M) x 64(N), BK=32. 256 threads = 8 warps (4 in M x 2 in N),
// each warp owns a 32x32 tile = 2x2 wmma m16n16k8 fragments.
// ---------------------------------------------------------------------------

#define LDA 40   // smem ld for A/B staging (32B-multiple row stride)
#define LDC 72   // smem ld for C staging

__device__ __forceinline__ void gemm_mainloop(
    const float* __restrict__ Ab, const float* __restrict__ Bb, int K,
    float* As, float* Bs,
    wmma::fragment<wmma::accumulator, 16, 16, 8, float> (&fc)[2][2],
    int tid, int wm, int wn)
{
#pragma unroll 1
    for (int kt = 0; kt < K; kt += 32) {
        // Stage A: 128x32 floats = 1024 float4, 4 per thread
#pragma unroll
        for (int it = 0; it < 4; it++) {
            int e = tid + it * 256;
            int r = e >> 3, c = (e & 7) << 2;
            float4 v = *(const float4*)(Ab + (size_t)r * K + kt + c);
            *(float4*)&As[r * LDA + c] = v;
        }
        // Stage B: 64x32 floats = 512 float4, 2 per thread
#pragma unroll
        for (int it = 0; it < 2; it++) {
            int e = tid + it * 256;
            int r = e >> 3, c = (e & 7) << 2;
            float4 v = *(const float4*)(Bb + (size_t)r * K + kt + c);
            *(float4*)&Bs[r * LDA + c] = v;
        }
        __syncthreads();

#pragma unroll
        for (int kk = 0; kk < 32; kk += 8) {
            wmma::fragment<wmma::matrix_a, 16, 16, 8, wmma::precision::tf32, wmma::row_major> fa[2];
            wmma::fragment<wmma::matrix_b, 16, 16, 8, wmma::precision::tf32, wmma::col_major> fb[2];
#pragma unroll
            for (int mi = 0; mi < 2; mi++) {
                wmma::load_matrix_sync(fa[mi], &As[(wm + mi * 16) * LDA + kk], LDA);
#pragma unroll
                for (int e = 0; e < fa[mi].num_elements; e++)
                    fa[mi].x[e] = wmma::__float_to_tf32(fa[mi].x[e]);
            }
#pragma unroll
            for (int ni = 0; ni < 2; ni++) {
                wmma::load_matrix_sync(fb[ni], &Bs[(wn + ni * 16) * LDA + kk], LDA);
#pragma unroll
                for (int e = 0; e < fb[ni].num_elements; e++)
                    fb[ni].x[e] = wmma::__float_to_tf32(fb[ni].x[e]);
            }
#pragma unroll
            for (int mi = 0; mi < 2; mi++)
#pragma unroll
                for (int ni = 0; ni < 2; ni++)
                    wmma::mma_sync(fc[mi][ni], fa[mi], fb[ni], fc[mi][ni]);
        }
        __syncthreads();
    }
}

__global__ void __launch_bounds__(256) qkv_gemm_kernel(
    const float* __restrict__ X, const float* __restrict__ W,
    const float* __restrict__ bias)
{
    __shared__ __align__(32) float smem[128 * LDC];
    float* As = smem;               // [128][LDA]
    float* Bs = smem + 128 * LDA;   // [64][LDA]
    const int K = DMODEL;
    const int tid = threadIdx.x;
    const int wid = tid >> 5;
    const int bn = blockIdx.x, bm = blockIdx.y;
    const int wm = (wid & 3) * 32;
    const int wn = (wid >> 2) * 32;

    wmma::fragment<wmma::accumulator, 16, 16, 8, float> fc[2][2];
#pragma unroll
    for (int mi = 0; mi < 2; mi++)
#pragma unroll
        for (int ni = 0; ni < 2; ni++) wmma::fill_fragment(fc[mi][ni], 0.f);

    gemm_mainloop(X + (size_t)bm * 128 * K, W + (size_t)bn * 64 * K, K,
                  As, Bs, fc, tid, wm, wn);

    // Epilogue: stage C tile in smem, then scatter to g_q/g_k/g_v
    float* Cs = smem;  // [128][LDC], reuse (post-sync)
#pragma unroll
    for (int mi = 0; mi < 2; mi++)
#pragma unroll
        for (int ni = 0; ni < 2; ni++)
            wmma::store_matrix_sync(&Cs[(wm + mi * 16) * LDC + wn + ni * 16],
                                    fc[mi][ni], LDC, wmma::mem_row_major);
    __syncthreads();

    const int nbase = bn * 64;
    const int which = nbase / DMODEL;
    const int hh = (nbase % DMODEL) / DH;
    float* dst = (which == 0) ? g_q : (which == 1) ? g_k : g_v;
#pragma unroll
    for (int it = 0; it < 8; it++) {
        int e = tid + it * 256;          // 2048 float4
        int r = e >> 4, c = (e & 15) << 2;
        int m = bm * 128 + r;
        int b = m >> 11, t = m & (T_SEQ - 1);
        float4 v = *(float4*)&Cs[r * LDC + c];
        v.x += bias[nbase + c];
        v.y += bias[nbase + c + 1];
        v.z += bias[nbase + c + 2];
        v.w += bias[nbase + c + 3];
        float* drow = dst + (((size_t)(b * NH + hh)) * T_SEQ + t) * DH;
        *(float4*)&drow[c] = v;
    }
}

__global__ void __launch_bounds__(256) proj_gemm_kernel(
    const float* __restrict__ A, const float* __restrict__ W,
    const float* __restrict__ bias, float* __restrict__ out)
{
    __shared__ __align__(32) float smem[128 * LDC];
    float* As = smem;
    float* Bs = smem + 128 * LDA;
    const int K = DMODEL;
    const int tid = threadIdx.x;
    const int wid = tid >> 5;
    const int bn = blockIdx.x, bm = blockIdx.y;
    const int wm = (wid & 3) * 32;
    const int wn = (wid >> 2) * 32;

    wmma::fragment<wmma::accumulator, 16, 16, 8, float> fc[2][2];
#pragma unroll
    for (int mi = 0; mi < 2; mi++)
#pragma unroll
        for (int ni = 0; ni < 2; ni++) wmma::fill_fragment(fc[mi][ni], 0.f);

    gemm_mainloop(A + (size_t)bm * 128 * K, W + (size_t)bn * 64 * K, K,
                  As, Bs, fc, tid, wm, wn);

    float* Cs = smem;
#pragma unroll
    for (int mi = 0; mi < 2; mi++)
#pragma unroll
        for (int ni = 0; ni < 2; ni++)
            wmma::store_matrix_sync(&Cs[(wm + mi * 16) * LDC + wn + ni * 16],
                                    fc[mi][ni], LDC, wmma::mem_row_major);
    __syncthreads();

    const int nbase = bn * 64;
#pragma unroll
    for (int it = 0; it < 8; it++) {
        int e = tid + it * 256;
        int r = e >> 4, c = (e & 15) << 2;
        int m = bm * 128 + r;
        float4 v = *(float4*)&Cs[r * LDC + c];
        v.x += bias[nbase + c];
        v.y += bias[nbase + c + 1];
        v.z += bias[nbase + c + 2];
        v.w += bias[nbase + c + 3];
        *(float4*)&out[(size_t)m * DMODEL + nbase + c] = v;
    }
}

// ---------------------------------------------------------------------------
// Flash attention with tf32 wmma.
// Block: 64 q-rows x (head, batch). 256 threads = 8 warps.
// S = (Q*scale) K^T via wmma (warp grid 4m x 2n of 16x32 subtiles),
// softmax in fp32 on smem, O += P V via wmma with O staged in smem.
// ---------------------------------------------------------------------------
#define LDS_A 72

extern __shared__ __align__(32) float s_attn[];

__global__ void __launch_bounds__(256) attn_kernel(float* __restrict__ out)
{
    float* Qs = s_attn;                 // [64][72]
    float* Ks = s_attn + 64 * LDS_A;    // [64][72]
    float* Vs = s_attn + 2 * 64 * LDS_A;
    float* Ss = s_attn + 3 * 64 * LDS_A;
    float* Os = s_attn + 4 * 64 * LDS_A;
    float* sm_m = s_attn + 5 * 64 * LDS_A;       // [64]
    float* sm_l = s_attn + 5 * 64 * LDS_A + 64;  // [64]

    const int tid = threadIdx.x;
    const int wid = tid >> 5;
    const int qt = blockIdx.x, h = blockIdx.y, b = blockIdx.z;
    const float scale = 0.125f;  // 1/sqrt(64)

    const size_t bh = ((size_t)(b * NH + h)) * T_SEQ * DH;
    const float* Qg = g_q + bh + (size_t)qt * 64 * DH;
    const float* Kg = g_k + bh;
    const float* Vg = g_v + bh;

    // Load + pre-scale Q; zero O
#pragma unroll
    for (int it = 0; it < 4; it++) {
        int e = tid + it * 256;          // 1024 float4 over 64x64
        int r = e >> 4, c = (e & 15) << 2;
        float4 v = *(const float4*)(Qg + r * DH + c);
        v.x *= scale; v.y *= scale; v.z *= scale; v.w *= scale;
        *(float4*)&Qs[r * LDS_A + c] = v;
        float4 z = make_float4(0.f, 0.f, 0.f, 0.f);
        *(float4*)&Os[r * LDS_A + c] = z;
    }
    if (tid < 64) { sm_m[tid] = -1e30f; sm_l[tid] = 0.f; }

    const int wm = (wid & 3) * 16;   // 16-row band in M
    const int wn = (wid >> 2) * 32;  // 32-col band in N (kv or d)

#pragma unroll 1
    for (int kt = 0; kt < T_SEQ; kt += 64) {
        __syncthreads();  // previous tile fully consumed
        // Stage K,V tiles
#pragma unroll
        for (int it = 0; it < 4; it++) {
            int e = tid + it * 256;
            int r = e >> 4, c = (e & 15) << 2;
            float4 kv = *(const float4*)(Kg + (size_t)(kt + r) * DH + c);
            *(float4*)&Ks[r * LDS_A + c] = kv;
            float4 vv = *(const float4*)(Vg + (size_t)(kt + r) * DH + c);
            *(float4*)&Vs[r * LDS_A + c] = vv;
        }
        __syncthreads();

        // ---- S = Q K^T ----
        {
            wmma::fragment<wmma::accumulator, 16, 16, 8, float> sc[2];
#pragma unroll
            for (int ni = 0; ni < 2; ni++) wmma::fill_fragment(sc[ni], 0.f);
#pragma unroll
            for (int kk = 0; kk < DH; kk += 8) {
                wmma::fragment<wmma::matrix_a, 16, 16, 8, wmma::precision::tf32, wmma::row_major> fa;
                wmma::load_matrix_sync(fa, &Qs[wm * LDS_A + kk], LDS_A);
#pragma unroll
                for (int e = 0; e < fa.num_elements; e++)
                    fa.x[e] = wmma::__float_to_tf32(fa.x[e]);
#pragma unroll
                for (int ni = 0; ni < 2; ni++) {
                    wmma::fragment<wmma::matrix_b, 16, 16, 8, wmma::precision::tf32, wmma::col_major> fb;
                    wmma::load_matrix_sync(fb, &Ks[(wn + ni * 16) * LDS_A + kk], LDS_A);
#pragma unroll
                    for (int e = 0; e < fb.num_elements; e++)
                        fb.x[e] = wmma::__float_to_tf32(fb.x[e]);
                    wmma::mma_sync(sc[ni], fa, fb, sc[ni]);
                }
            }
#pragma unroll
            for (int ni = 0; ni < 2; ni++)
                wmma::store_matrix_sync(&Ss[wm * LDS_A + wn + ni * 16], sc[ni],
                                        LDS_A, wmma::mem_row_major);
        }
        __syncthreads();

        // ---- Online softmax on Ss; rescale Os ----
        {
            int row = tid >> 2, sub = tid & 3;
            float* srow = &Ss[row * LDS_A + sub * 16];
            float mold = sm_m[row];
            float rmax = srow[0];
#pragma unroll
            for (int c = 1; c < 16; c++) rmax = fmaxf(rmax, srow[c]);
            rmax = fmaxf(rmax, __shfl_xor_sync(0xffffffffu, rmax, 1));
            rmax = fmaxf(rmax, __shfl_xor_sync(0xffffffffu, rmax, 2));
            float mnew = fmaxf(mold, rmax);
            float corr = __expf(mold - mnew);
            float rsum = 0.f;
#pragma unroll
            for (int c = 0; c < 16; c++) {
                float v = __expf(srow[c] - mnew);
                srow[c] = v;
                rsum += v;
            }
            rsum += __shfl_xor_sync(0xffffffffu, rsum, 1);
            rsum += __shfl_xor_sync(0xffffffffu, rsum, 2);
            if (sub == 0) {
                sm_m[row] = mnew;
                sm_l[row] = sm_l[row] * corr + rsum;
            }
            float* orow = &Os[row * LDS_A + sub * 16];
#pragma unroll
            for (int c = 0; c < 16; c++) orow[c] *= corr;
        }
        __syncthreads();

        // ---- O += P V ----
        {
#pragma unroll
            for (int ni = 0; ni < 2; ni++) {
                wmma::fragment<wmma::accumulator, 16, 16, 8, float> oc;
                wmma::load_matrix_sync(oc, &Os[wm * LDS_A + wn + ni * 16],
                                       LDS_A, wmma::mem_row_major);
#pragma unroll
                for (int kk = 0; kk < 64; kk += 8) {
                    wmma::fragment<wmma::matrix_a, 16, 16, 8, wmma::precision::tf32, wmma::row_major> fp;
                    wmma::load_matrix_sync(fp, &Ss[wm * LDS_A + kk], LDS_A);
#pragma unroll
                    for (int e = 0; e < fp.num_elements; e++)
                        fp.x[e] = wmma::__float_to_tf32(fp.x[e]);
                    wmma::fragment<wmma::matrix_b, 16, 16, 8, wmma::precision::tf32, wmma::row_major> fv;
                    wmma::load_matrix_sync(fv, &Vs[kk * LDS_A + wn + ni * 16], LDS_A);
#pragma unroll
                    for (int e = 0; e < fv.num_elements; e++)
                        fv.x[e] = wmma::__float_to_tf32(fv.x[e]);
                    wmma::mma_sync(oc, fp, fv, oc);
                }
                wmma::store_matrix_sync(&Os[wm * LDS_A + wn + ni * 16], oc,
                                        LDS_A, wmma::mem_row_major);
            }
        }
    }
    __syncthreads();

    // Normalize and write [B,T,H*Dh]
    {
        int row = tid >> 2, sub = tid & 3;
        float inv = 1.f / sm_l[row];
        int t = qt * 64 + row;
        float* drow = out + ((size_t)b * T_SEQ + t) * DMODEL + h * DH + sub * 16;
        float* orow = &Os[row * LDS_A + sub * 16];
#pragma unroll
        for (int c = 0; c < 16; c += 4) {
            float4 v = *(float4*)&orow[c];
            v.x *= inv; v.y *= inv; v.z *= inv; v.w *= inv;
            *(float4*)&drow[c] = v;
        }
    }
}

// ---------------------------------------------------------------------------
extern "C" void kernel_launch(void* const* d_in, const int* in_sizes, int n_in,
                              void* d_out, int out_size)
{
    const float* x      = (const float*)d_in[0];
    const float* W_qkv  = (const float*)d_in[1];
    const float* b_qkv  = (const float*)d_in[2];
    const float* W_proj = (const float*)d_in[3];
    const float* b_proj = (const float*)d_in[4];
    float* out = (float*)d_out;

    const int ATTN_SMEM = (5 * 64 * LDS_A + 128) * (int)sizeof(float);  // 92672 B
    cudaFuncSetAttribute(attn_kernel,
                         cudaFuncAttributeMaxDynamicSharedMemorySize, ATTN_SMEM);

    float* attn_scratch;
    cudaGetSymbolAddress((void**)&attn_scratch, g_attn);

    // 1) QKV GEMM + scatter to per-head Q/K/V
    {
        dim3 grid(3 * DMODEL / 64, (NB * T_SEQ) / 128);  // (36, 64)
        qkv_gemm_kernel<<<grid, 256>>>(x, W_qkv, b_qkv);
    }
    // 2) Flash attention
    {
        dim3 grid(T_SEQ / 64, NH, NB);  // (32, 12, 4)
        attn_kernel<<<grid, 256, ATTN_SMEM>>>(attn_scratch);
    }
    // 3) Output projection
    {
        dim3 grid(DMODEL / 64, (NB * T_SEQ) / 128);  // (12, 64)
        proj_gemm_kernel<<<grid, 256>>>(attn_scratch, W_proj, b_proj, out);
    }
}

// round 3
// speedup vs baseline: 2.8919x; 1.8104x over previous
#include <cuda_runtime.h>
#include <mma.h>
#include <cstdint>
using namespace nvcuda;

#define T_SEQ  2048
#define NB     4
#define NH     12
#define DH     64
#define DMODEL 768

// Scratch (device globals — no runtime allocation allowed)
__device__ float g_q[NB * NH * T_SEQ * DH];
__device__ float g_k[NB * NH * T_SEQ * DH];
__device__ float g_v[NB * NH * T_SEQ * DH];
__device__ float g_attn[NB * T_SEQ * DMODEL];

__device__ __forceinline__ float to_tf32(float x) {
    float r;
    asm("cvt.rna.tf32.f32 %0, %1;" : "=f"(r) : "f"(x));
    return r;
}
__device__ __forceinline__ float4 to_tf32_v4(float4 v) {
    v.x = to_tf32(v.x); v.y = to_tf32(v.y);
    v.z = to_tf32(v.z); v.w = to_tf32(v.w);
    return v;
}

// mma.m16n8k8 tf32: D += A*B, A row-major 16x8, B col-major 8x8
__device__ __forceinline__ void mma_tf32(float (&d)[4], const float (&a)[4], const float (&b)[2]) {
    asm volatile(
        "mma.sync.aligned.m16n8k8.row.col.f32.tf32.tf32.f32 "
        "{%0,%1,%2,%3}, {%4,%5,%6,%7}, {%8,%9}, {%0,%1,%2,%3};\n"
        : "+f"(d[0]), "+f"(d[1]), "+f"(d[2]), "+f"(d[3])
        : "r"(__float_as_uint(a[0])), "r"(__float_as_uint(a[1])),
          "r"(__float_as_uint(a[2])), "r"(__float_as_uint(a[3])),
          "r"(__float_as_uint(b[0])), "r"(__float_as_uint(b[1])));
}

// ---------------------------------------------------------------------------
// tf32 wmma GEMM: out[m,n] = sum_k A[m,k] * W[n,k] + bias[n]
// 128(M) x 64(N) tile, BK=32, 256 threads = 8 warps (4m x 2n), 32x32 per warp.
// tf32 conversion at staging; 2-stage smem double buffering.
// ---------------------------------------------------------------------------
#define GLD 40   // smem row stride for A/B stages
#define LDC 72   // smem row stride for C staging
#define GEMM_SMEM (2 * 192 * GLD * 4)   // 61440 B

extern __shared__ __align__(16) float g_smem[];

__device__ __forceinline__ void gemm_core(
    const float* __restrict__ Ab, const float* __restrict__ Bb, int K,
    wmma::fragment<wmma::accumulator, 16, 16, 8, float> (&fc)[2][2],
    int tid, int wm, int wn)
{
    float* stage[2] = { g_smem, g_smem + 192 * GLD };

    float4 ra[4], rb[2];
    // prefetch kt=0
#pragma unroll
    for (int it = 0; it < 4; it++) {
        int e = tid + it * 256, r = e >> 3, c = (e & 7) << 2;
        ra[it] = *(const float4*)(Ab + (size_t)r * K + c);
    }
#pragma unroll
    for (int it = 0; it < 2; it++) {
        int e = tid + it * 256, r = e >> 3, c = (e & 7) << 2;
        rb[it] = *(const float4*)(Bb + (size_t)r * K + c);
    }
    {
        float* As = stage[0];
        float* Bs = stage[0] + 128 * GLD;
#pragma unroll
        for (int it = 0; it < 4; it++) {
            int e = tid + it * 256, r = e >> 3, c = (e & 7) << 2;
            *(float4*)&As[r * GLD + c] = to_tf32_v4(ra[it]);
        }
#pragma unroll
        for (int it = 0; it < 2; it++) {
            int e = tid + it * 256, r = e >> 3, c = (e & 7) << 2;
            *(float4*)&Bs[r * GLD + c] = to_tf32_v4(rb[it]);
        }
    }
    __syncthreads();

    int buf = 0;
#pragma unroll 1
    for (int kt = 32; kt < K; kt += 32) {
        // prefetch next k-tile to registers
#pragma unroll
        for (int it = 0; it < 4; it++) {
            int e = tid + it * 256, r = e >> 3, c = (e & 7) << 2;
            ra[it] = *(const float4*)(Ab + (size_t)r * K + kt + c);
        }
#pragma unroll
        for (int it = 0; it < 2; it++) {
            int e = tid + it * 256, r = e >> 3, c = (e & 7) << 2;
            rb[it] = *(const float4*)(Bb + (size_t)r * K + kt + c);
        }
        // compute current stage
        {
            float* As = stage[buf];
            float* Bs = stage[buf] + 128 * GLD;
#pragma unroll
            for (int kk = 0; kk < 32; kk += 8) {
                wmma::fragment<wmma::matrix_a, 16, 16, 8, wmma::precision::tf32, wmma::row_major> fa[2];
                wmma::fragment<wmma::matrix_b, 16, 16, 8, wmma::precision::tf32, wmma::col_major> fb[2];
#pragma unroll
                for (int mi = 0; mi < 2; mi++)
                    wmma::load_matrix_sync(fa[mi], &As[(wm + mi * 16) * GLD + kk], GLD);
#pragma unroll
                for (int ni = 0; ni < 2; ni++)
                    wmma::load_matrix_sync(fb[ni], &Bs[(wn + ni * 16) * GLD + kk], GLD);
#pragma unroll
                for (int mi = 0; mi < 2; mi++)
#pragma unroll
                    for (int ni = 0; ni < 2; ni++)
                        wmma::mma_sync(fc[mi][ni], fa[mi], fb[ni], fc[mi][ni]);
            }
        }
        // store prefetched into other stage
        {
            float* As = stage[buf ^ 1];
            float* Bs = stage[buf ^ 1] + 128 * GLD;
#pragma unroll
            for (int it = 0; it < 4; it++) {
                int e = tid + it * 256, r = e >> 3, c = (e & 7) << 2;
                *(float4*)&As[r * GLD + c] = to_tf32_v4(ra[it]);
            }
#pragma unroll
            for (int it = 0; it < 2; it++) {
                int e = tid + it * 256, r = e >> 3, c = (e & 7) << 2;
                *(float4*)&Bs[r * GLD + c] = to_tf32_v4(rb[it]);
            }
        }
        __syncthreads();
        buf ^= 1;
    }
    // last tile
    {
        float* As = stage[buf];
        float* Bs = stage[buf] + 128 * GLD;
#pragma unroll
        for (int kk = 0; kk < 32; kk += 8) {
            wmma::fragment<wmma::matrix_a, 16, 16, 8, wmma::precision::tf32, wmma::row_major> fa[2];
            wmma::fragment<wmma::matrix_b, 16, 16, 8, wmma::precision::tf32, wmma::col_major> fb[2];
#pragma unroll
            for (int mi = 0; mi < 2; mi++)
                wmma::load_matrix_sync(fa[mi], &As[(wm + mi * 16) * GLD + kk], GLD);
#pragma unroll
            for (int ni = 0; ni < 2; ni++)
                wmma::load_matrix_sync(fb[ni], &Bs[(wn + ni * 16) * GLD + kk], GLD);
#pragma unroll
            for (int mi = 0; mi < 2; mi++)
#pragma unroll
                for (int ni = 0; ni < 2; ni++)
                    wmma::mma_sync(fc[mi][ni], fa[mi], fb[ni], fc[mi][ni]);
        }
    }
    __syncthreads();  // before Cs reuse of smem
}

__global__ void __launch_bounds__(256) qkv_gemm_kernel(
    const float* __restrict__ X, const float* __restrict__ W,
    const float* __restrict__ bias)
{
    const int K = DMODEL;
    const int tid = threadIdx.x;
    const int wid = tid >> 5;
    const int bn = blockIdx.x, bm = blockIdx.y;
    const int wm = (wid & 3) * 32, wn = (wid >> 2) * 32;

    wmma::fragment<wmma::accumulator, 16, 16, 8, float> fc[2][2];
#pragma unroll
    for (int mi = 0; mi < 2; mi++)
#pragma unroll
        for (int ni = 0; ni < 2; ni++) wmma::fill_fragment(fc[mi][ni], 0.f);

    gemm_core(X + (size_t)bm * 128 * K, W + (size_t)bn * 64 * K, K, fc, tid, wm, wn);

    float* Cs = g_smem;  // [128][LDC]
#pragma unroll
    for (int mi = 0; mi < 2; mi++)
#pragma unroll
        for (int ni = 0; ni < 2; ni++)
            wmma::store_matrix_sync(&Cs[(wm + mi * 16) * LDC + wn + ni * 16],
                                    fc[mi][ni], LDC, wmma::mem_row_major);
    __syncthreads();

    const int nbase = bn * 64;
    const int which = nbase / DMODEL;
    const int hh = (nbase % DMODEL) / DH;
    float* dst = (which == 0) ? g_q : (which == 1) ? g_k : g_v;
#pragma unroll
    for (int it = 0; it < 8; it++) {
        int e = tid + it * 256;
        int r = e >> 4, c = (e & 15) << 2;
        int m = bm * 128 + r;
        int b = m >> 11, t = m & (T_SEQ - 1);
        float4 v = *(float4*)&Cs[r * LDC + c];
        v.x += bias[nbase + c];     v.y += bias[nbase + c + 1];
        v.z += bias[nbase + c + 2]; v.w += bias[nbase + c + 3];
        float* drow = dst + (((size_t)(b * NH + hh)) * T_SEQ + t) * DH;
        *(float4*)&drow[c] = v;
    }
}

__global__ void __launch_bounds__(256) proj_gemm_kernel(
    const float* __restrict__ A, const float* __restrict__ W,
    const float* __restrict__ bias, float* __restrict__ out)
{
    const int K = DMODEL;
    const int tid = threadIdx.x;
    const int wid = tid >> 5;
    const int bn = blockIdx.x, bm = blockIdx.y;
    const int wm = (wid & 3) * 32, wn = (wid >> 2) * 32;

    wmma::fragment<wmma::accumulator, 16, 16, 8, float> fc[2][2];
#pragma unroll
    for (int mi = 0; mi < 2; mi++)
#pragma unroll
        for (int ni = 0; ni < 2; ni++) wmma::fill_fragment(fc[mi][ni], 0.f);

    gemm_core(A + (size_t)bm * 128 * K, W + (size_t)bn * 64 * K, K, fc, tid, wm, wn);

    float* Cs = g_smem;
#pragma unroll
    for (int mi = 0; mi < 2; mi++)
#pragma unroll
        for (int ni = 0; ni < 2; ni++)
            wmma::store_matrix_sync(&Cs[(wm + mi * 16) * LDC + wn + ni * 16],
                                    fc[mi][ni], LDC, wmma::mem_row_major);
    __syncthreads();

    const int nbase = bn * 64;
#pragma unroll
    for (int it = 0; it < 8; it++) {
        int e = tid + it * 256;
        int r = e >> 4, c = (e & 15) << 2;
        int m = bm * 128 + r;
        float4 v = *(float4*)&Cs[r * LDC + c];
        v.x += bias[nbase + c];     v.y += bias[nbase + c + 1];
        v.z += bias[nbase + c + 2]; v.w += bias[nbase + c + 3];
        *(float4*)&out[(size_t)m * DMODEL + nbase + c] = v;
    }
}

// ---------------------------------------------------------------------------
// Register-resident flash attention with raw mma.m16n8k8 tf32.
// 128 threads = 4 warps; each warp owns 16 q-rows. S and O live in
// accumulator registers; softmax stats per-row in registers (quad shfl);
// P takes a warp-local smem round-trip for the A-operand layout shuffle.
// ---------------------------------------------------------------------------
#define AT_LD 68
#define ATTN_SMEM (4 * 64 * AT_LD * 4)   // Qs,Ks,Vs,Ps = 69632 B

__global__ void __launch_bounds__(128) attn_kernel(float* __restrict__ out)
{
    float* Qs = g_smem;                  // [64][AT_LD] tf32(Q*scale)
    float* Ks = g_smem + 64 * AT_LD;     // tf32
    float* Vs = g_smem + 2 * 64 * AT_LD; // tf32
    float* Ps = g_smem + 3 * 64 * AT_LD; // tf32 probs (warp-local)

    const int tid = threadIdx.x;
    const int warp = tid >> 5, lane = tid & 31;
    const int grp = lane >> 2, q4 = lane & 3;   // quad structure
    const int wm = warp * 16;
    const int qt = blockIdx.x, h = blockIdx.y, b = blockIdx.z;
    const float scale = 0.125f;

    const size_t bh = ((size_t)(b * NH + h)) * T_SEQ * DH;
    const float* Qg = g_q + bh + (size_t)qt * 64 * DH;
    const float* Kg = g_k + bh;
    const float* Vg = g_v + bh;

    // Stage Q (scaled + tf32)
#pragma unroll
    for (int it = 0; it < 8; it++) {
        int e = tid + it * 128;
        int r = e >> 4, c = (e & 15) << 2;
        float4 v = *(const float4*)(Qg + r * DH + c);
        v.x *= scale; v.y *= scale; v.z *= scale; v.w *= scale;
        *(float4*)&Qs[r * AT_LD + c] = to_tf32_v4(v);
    }

    float o[8][4];
#pragma unroll
    for (int j = 0; j < 8; j++)
#pragma unroll
        for (int c = 0; c < 4; c++) o[j][c] = 0.f;
    float m_lo = -1e30f, m_hi = -1e30f, l_lo = 0.f, l_hi = 0.f;

#pragma unroll 1
    for (int kt = 0; kt < T_SEQ; kt += 64) {
        __syncthreads();   // previous tile consumed (also orders Q on iter 0)
#pragma unroll
        for (int it = 0; it < 8; it++) {
            int e = tid + it * 128;
            int r = e >> 4, c = (e & 15) << 2;
            float4 kv = *(const float4*)(Kg + (size_t)(kt + r) * DH + c);
            *(float4*)&Ks[r * AT_LD + c] = to_tf32_v4(kv);
            float4 vv = *(const float4*)(Vg + (size_t)(kt + r) * DH + c);
            *(float4*)&Vs[r * AT_LD + c] = to_tf32_v4(vv);
        }
        __syncthreads();

        // ---- S = Q K^T : 8 n-tiles of 8 kv-cols, accum in registers ----
        float s[8][4];
#pragma unroll
        for (int j = 0; j < 8; j++)
#pragma unroll
            for (int c = 0; c < 4; c++) s[j][c] = 0.f;
#pragma unroll
        for (int kk = 0; kk < 8; kk++) {
            float a[4];
            a[0] = Qs[(wm + grp) * AT_LD + kk * 8 + q4];
            a[1] = Qs[(wm + grp + 8) * AT_LD + kk * 8 + q4];
            a[2] = Qs[(wm + grp) * AT_LD + kk * 8 + q4 + 4];
            a[3] = Qs[(wm + grp + 8) * AT_LD + kk * 8 + q4 + 4];
#pragma unroll
            for (int j = 0; j < 8; j++) {
                float bb[2];
                bb[0] = Ks[(j * 8 + grp) * AT_LD + kk * 8 + q4];
                bb[1] = Ks[(j * 8 + grp) * AT_LD + kk * 8 + q4 + 4];
                mma_tf32(s[j], a, bb);
            }
        }

        // ---- Online softmax in registers ----
        float tm_lo = -1e30f, tm_hi = -1e30f;
#pragma unroll
        for (int j = 0; j < 8; j++) {
            tm_lo = fmaxf(tm_lo, fmaxf(s[j][0], s[j][1]));
            tm_hi = fmaxf(tm_hi, fmaxf(s[j][2], s[j][3]));
        }
        tm_lo = fmaxf(tm_lo, __shfl_xor_sync(0xffffffffu, tm_lo, 1));
        tm_lo = fmaxf(tm_lo, __shfl_xor_sync(0xffffffffu, tm_lo, 2));
        tm_hi = fmaxf(tm_hi, __shfl_xor_sync(0xffffffffu, tm_hi, 1));
        tm_hi = fmaxf(tm_hi, __shfl_xor_sync(0xffffffffu, tm_hi, 2));

        float mn_lo = fmaxf(m_lo, tm_lo);
        float mn_hi = fmaxf(m_hi, tm_hi);
        float corr_lo = __expf(m_lo - mn_lo);
        float corr_hi = __expf(m_hi - mn_hi);

        float rs_lo = 0.f, rs_hi = 0.f;
#pragma unroll
        for (int j = 0; j < 8; j++) {
            s[j][0] = __expf(s[j][0] - mn_lo);
            s[j][1] = __expf(s[j][1] - mn_lo);
            s[j][2] = __expf(s[j][2] - mn_hi);
            s[j][3] = __expf(s[j][3] - mn_hi);
            rs_lo += s[j][0] + s[j][1];
            rs_hi += s[j][2] + s[j][3];
        }
        rs_lo += __shfl_xor_sync(0xffffffffu, rs_lo, 1);
        rs_lo += __shfl_xor_sync(0xffffffffu, rs_lo, 2);
        rs_hi += __shfl_xor_sync(0xffffffffu, rs_hi, 1);
        rs_hi += __shfl_xor_sync(0xffffffffu, rs_hi, 2);

        l_lo = l_lo * corr_lo + rs_lo;  m_lo = mn_lo;
        l_hi = l_hi * corr_hi + rs_hi;  m_hi = mn_hi;

#pragma unroll
        for (int j = 0; j < 8; j++) {
            o[j][0] *= corr_lo; o[j][1] *= corr_lo;
            o[j][2] *= corr_hi; o[j][3] *= corr_hi;
        }

        // ---- Store P (tf32) to warp-local smem for A-operand reload ----
#pragma unroll
        for (int j = 0; j < 8; j++) {
            float2 plo = make_float2(to_tf32(s[j][0]), to_tf32(s[j][1]));
            float2 phi = make_float2(to_tf32(s[j][2]), to_tf32(s[j][3]));
            *(float2*)&Ps[(wm + grp) * AT_LD + j * 8 + 2 * q4] = plo;
            *(float2*)&Ps[(wm + grp + 8) * AT_LD + j * 8 + 2 * q4] = phi;
        }
        __syncwarp();

        // ---- O += P V ----
#pragma unroll
        for (int kk = 0; kk < 8; kk++) {
            float a[4];
            a[0] = Ps[(wm + grp) * AT_LD + kk * 8 + q4];
            a[1] = Ps[(wm + grp + 8) * AT_LD + kk * 8 + q4];
            a[2] = Ps[(wm + grp) * AT_LD + kk * 8 + q4 + 4];
            a[3] = Ps[(wm + grp + 8) * AT_LD + kk * 8 + q4 + 4];
#pragma unroll
            for (int j = 0; j < 8; j++) {
                float bb[2];
                bb[0] = Vs[(kk * 8 + q4) * AT_LD + j * 8 + grp];
                bb[1] = Vs[(kk * 8 + q4 + 4) * AT_LD + j * 8 + grp];
                mma_tf32(o[j], a, bb);
            }
        }
        __syncwarp();
    }

    // ---- Normalize + write out [B,T,H*Dh] ----
    float inv_lo = 1.f / l_lo;
    float inv_hi = 1.f / l_hi;
    int t_lo = qt * 64 + wm + grp;
    int t_hi = t_lo + 8;
    float* row_lo = out + ((size_t)b * T_SEQ + t_lo) * DMODEL + h * DH;
    float* row_hi = out + ((size_t)b * T_SEQ + t_hi) * DMODEL + h * DH;
#pragma unroll
    for (int j = 0; j < 8; j++) {
        float2 vlo = make_float2(o[j][0] * inv_lo, o[j][1] * inv_lo);
        float2 vhi = make_float2(o[j][2] * inv_hi, o[j][3] * inv_hi);
        *(float2*)&row_lo[j * 8 + 2 * q4] = vlo;
        *(float2*)&row_hi[j * 8 + 2 * q4] = vhi;
    }
}

// ---------------------------------------------------------------------------
extern "C" void kernel_launch(void* const* d_in, const int* in_sizes, int n_in,
                              void* d_out, int out_size)
{
    const float* x      = (const float*)d_in[0];
    const float* W_qkv  = (const float*)d_in[1];
    const float* b_qkv  = (const float*)d_in[2];
    const float* W_proj = (const float*)d_in[3];
    const float* b_proj = (const float*)d_in[4];
    float* out = (float*)d_out;

    cudaFuncSetAttribute(qkv_gemm_kernel,
                         cudaFuncAttributeMaxDynamicSharedMemorySize, GEMM_SMEM);
    cudaFuncSetAttribute(proj_gemm_kernel,
                         cudaFuncAttributeMaxDynamicSharedMemorySize, GEMM_SMEM);
    cudaFuncSetAttribute(attn_kernel,
                         cudaFuncAttributeMaxDynamicSharedMemorySize, ATTN_SMEM);

    float* attn_scratch;
    cudaGetSymbolAddress((void**)&attn_scratch, g_attn);

    // 1) QKV GEMM + scatter to per-head Q/K/V
    {
        dim3 grid(3 * DMODEL / 64, (NB * T_SEQ) / 128);  // (36, 64)
        qkv_gemm_kernel<<<grid, 256, GEMM_SMEM>>>(x, W_qkv, b_qkv);
    }
    // 2) Flash attention
    {
        dim3 grid(T_SEQ / 64, NH, NB);  // (32, 12, 4)
        attn_kernel<<<grid, 128, ATTN_SMEM>>>(attn_scratch);
    }
    // 3) Output projection
    {
        dim3 grid(DMODEL / 64, (NB * T_SEQ) / 128);  // (12, 64)
        proj_gemm_kernel<<<grid, 256, GEMM_SMEM>>>(attn_scratch, W_proj, b_proj, out);
    }
}

// round 5
// speedup vs baseline: 4.0842x; 1.4123x over previous
#include <cuda_runtime.h>
#include <cstdint>

#define T_SEQ  2048
#define NB     4
#define NH     12
#define DH     64
#define DMODEL 768

// Scratch (device globals — no runtime allocation allowed)
// g_q, g_k: [B][H][T][Dh] (tf32-rounded; q pre-scaled by 1/8)
// g_v:      [B][H][Dh][T] (TRANSPOSED, tf32-rounded)
__device__ float g_q[NB * NH * T_SEQ * DH];
__device__ float g_k[NB * NH * T_SEQ * DH];
__device__ float g_v[NB * NH * T_SEQ * DH];
__device__ float g_attn[NB * T_SEQ * DMODEL];

__device__ __forceinline__ float to_tf32(float x) {
    float r;
    asm("cvt.rna.tf32.f32 %0, %1;" : "=f"(r) : "f"(x));
    return r;
}
__device__ __forceinline__ float4 to_tf32_v4(float4 v) {
    v.x = to_tf32(v.x); v.y = to_tf32(v.y);
    v.z = to_tf32(v.z); v.w = to_tf32(v.w);
    return v;
}

__device__ __forceinline__ void ldsm4(uint32_t (&r)[4], uint32_t addr) {
    asm volatile("ldmatrix.sync.aligned.m8n8.x4.shared.b16 {%0,%1,%2,%3}, [%4];\n"
                 : "=r"(r[0]), "=r"(r[1]), "=r"(r[2]), "=r"(r[3]) : "r"(addr));
}

// mma.m16n8k8 tf32: D += A*B
__device__ __forceinline__ void mma8(float (&d)[4], const uint32_t (&a)[4],
                                     uint32_t b0, uint32_t b1) {
    asm volatile(
        "mma.sync.aligned.m16n8k8.row.col.f32.tf32.tf32.f32 "
        "{%0,%1,%2,%3}, {%4,%5,%6,%7}, {%8,%9}, {%0,%1,%2,%3};\n"
        : "+f"(d[0]), "+f"(d[1]), "+f"(d[2]), "+f"(d[3])
        : "r"(a[0]), "r"(a[1]), "r"(a[2]), "r"(a[3]), "r"(b0), "r"(b1));
}

#define CP16(dst_u32, src_ptr) \
    asm volatile("cp.async.cg.shared.global [%0], [%1], 16;\n" \
                 :: "r"(dst_u32), "l"(src_ptr) : "memory")
#define CP_COMMIT() asm volatile("cp.async.commit_group;\n" ::: "memory")
#define CP_WAIT_ALL() asm volatile("cp.async.wait_all;\n" ::: "memory")

// ---------------------------------------------------------------------------
// GEMM: out[m,n] = sum_k A[m,k]*W[n,k] (+bias later). 128M x 64N, BK=32,
// 256 thr = 8 warps (4m x 2n), 32x32 per warp. raw mma + ldmatrix,
// tf32 conversion at staging, 2-stage double buffer.
// ---------------------------------------------------------------------------
#define GLD 36
#define STAGEF (192 * GLD)               // floats per stage
#define GEMM_SMEM (2 * STAGEF * 4)       // 55296 B
#define LDC 72

extern __shared__ __align__(16) float g_smem[];

__device__ __forceinline__ void gemm_stage(
    float* dst, const float4 (&ra)[4], const float4 (&rb)[2], int tid)
{
    float* As = dst;
    float* Bs = dst + 128 * GLD;
#pragma unroll
    for (int it = 0; it < 4; it++) {
        int e = tid + it * 256, r = e >> 3, c = (e & 7) << 2;
        *(float4*)&As[r * GLD + c] = to_tf32_v4(ra[it]);
    }
#pragma unroll
    for (int it = 0; it < 2; it++) {
        int e = tid + it * 256, r = e >> 3, c = (e & 7) << 2;
        *(float4*)&Bs[r * GLD + c] = to_tf32_v4(rb[it]);
    }
}

__device__ __forceinline__ void gemm_compute(
    uint32_t a_base, uint32_t b_base, float (&acc)[2][4][4])
{
#pragma unroll
    for (int kk = 0; kk < 32; kk += 8) {
        uint32_t a0[4], a1[4];
        ldsm4(a0, a_base + kk * 4);
        ldsm4(a1, a_base + 16 * GLD * 4 + kk * 4);
#pragma unroll
        for (int np = 0; np < 2; np++) {
            uint32_t b[4];
            ldsm4(b, b_base + np * 16 * GLD * 4 + kk * 4);
            mma8(acc[0][np * 2],     a0, b[0], b[1]);
            mma8(acc[0][np * 2 + 1], a0, b[2], b[3]);
            mma8(acc[1][np * 2],     a1, b[0], b[1]);
            mma8(acc[1][np * 2 + 1], a1, b[2], b[3]);
        }
    }
}

__device__ __forceinline__ void gemm_core(
    const float* __restrict__ Ab, const float* __restrict__ Bb, int K,
    float (&acc)[2][4][4], int tid, int wm, int wn)
{
    const int lane = tid & 31;
    uint32_t smem_u = (uint32_t)__cvta_generic_to_shared(g_smem);
    uint32_t a_base = smem_u + ((wm + (lane & 15)) * GLD + ((lane >> 4) << 2)) * 4;
    uint32_t b_base = smem_u + (128 * GLD +
        (wn + ((lane >> 4) << 3) + (lane & 7)) * GLD + (((lane >> 3) & 1) << 2)) * 4;

    float4 ra[4], rb[2];
#pragma unroll
    for (int it = 0; it < 4; it++) {
        int e = tid + it * 256, r = e >> 3, c = (e & 7) << 2;
        ra[it] = *(const float4*)(Ab + (size_t)r * K + c);
    }
#pragma unroll
    for (int it = 0; it < 2; it++) {
        int e = tid + it * 256, r = e >> 3, c = (e & 7) << 2;
        rb[it] = *(const float4*)(Bb + (size_t)r * K + c);
    }
    gemm_stage(g_smem, ra, rb, tid);
    __syncthreads();

    int buf = 0;
#pragma unroll 1
    for (int kt = 32; kt < K; kt += 32) {
#pragma unroll
        for (int it = 0; it < 4; it++) {
            int e = tid + it * 256, r = e >> 3, c = (e & 7) << 2;
            ra[it] = *(const float4*)(Ab + (size_t)r * K + kt + c);
        }
#pragma unroll
        for (int it = 0; it < 2; it++) {
            int e = tid + it * 256, r = e >> 3, c = (e & 7) << 2;
            rb[it] = *(const float4*)(Bb + (size_t)r * K + kt + c);
        }
        gemm_compute(a_base + buf * STAGEF * 4, b_base + buf * STAGEF * 4, acc);
        gemm_stage(g_smem + (buf ^ 1) * STAGEF, ra, rb, tid);
        __syncthreads();
        buf ^= 1;
    }
    gemm_compute(a_base + buf * STAGEF * 4, b_base + buf * STAGEF * 4, acc);
    __syncthreads();  // before Cs reuse
}

__device__ __forceinline__ void gemm_store_cs(
    float (&acc)[2][4][4], float* Cs, int lane, int wm, int wn)
{
    const int grp = lane >> 2, q4 = lane & 3;
#pragma unroll
    for (int mi = 0; mi < 2; mi++)
#pragma unroll
        for (int n8 = 0; n8 < 4; n8++)
#pragma unroll
            for (int hh = 0; hh < 2; hh++) {
                int row = wm + mi * 16 + grp + 8 * hh;
                int col = wn + n8 * 8 + 2 * q4;
                *(float2*)&Cs[row * LDC + col] =
                    make_float2(acc[mi][n8][2 * hh], acc[mi][n8][2 * hh + 1]);
            }
}

__global__ void __launch_bounds__(256) qkv_gemm_kernel(
    const float* __restrict__ X, const float* __restrict__ W,
    const float* __restrict__ bias)
{
    const int K = DMODEL;
    const int tid = threadIdx.x, lane = tid & 31, wid = tid >> 5;
    const int bn = blockIdx.x, bm = blockIdx.y;
    const int wm = (wid & 3) * 32, wn = (wid >> 2) * 32;

    float acc[2][4][4];
#pragma unroll
    for (int mi = 0; mi < 2; mi++)
#pragma unroll
        for (int n8 = 0; n8 < 4; n8++)
#pragma unroll
            for (int c = 0; c < 4; c++) acc[mi][n8][c] = 0.f;

    gemm_core(X + (size_t)bm * 128 * K, W + (size_t)bn * 64 * K, K, acc, tid, wm, wn);

    float* Cs = g_smem;
    gemm_store_cs(acc, Cs, lane, wm, wn);
    __syncthreads();

    const int nbase = bn * 64;
    const int which = nbase / DMODEL;
    const int hh = (nbase % DMODEL) / DH;

    if (which == 2) {
        // V: bias + tf32, store TRANSPOSED [b][h][d][t]
#pragma unroll
        for (int it = 0; it < 8; it++) {
            int e = tid + it * 256;
            int r = e >> 4, c = (e & 15) << 2;
            int m = bm * 128 + r;
            int b = m >> 11, t = m & (T_SEQ - 1);
            float4 v = *(float4*)&Cs[r * LDC + c];
            v.x = to_tf32(v.x + bias[nbase + c]);
            v.y = to_tf32(v.y + bias[nbase + c + 1]);
            v.z = to_tf32(v.z + bias[nbase + c + 2]);
            v.w = to_tf32(v.w + bias[nbase + c + 3]);
            float* base = g_v + ((size_t)(b * NH + hh) * DH + c) * T_SEQ + t;
            base[0] = v.x;
            base[T_SEQ] = v.y;
            base[2 * T_SEQ] = v.z;
            base[3 * T_SEQ] = v.w;
        }
    } else {
        float* dst = (which == 0) ? g_q : g_k;
        const float qscale = (which == 0) ? 0.125f : 1.0f;
#pragma unroll
        for (int it = 0; it < 8; it++) {
            int e = tid + it * 256;
            int r = e >> 4, c = (e & 15) << 2;
            int m = bm * 128 + r;
            int b = m >> 11, t = m & (T_SEQ - 1);
            float4 v = *(float4*)&Cs[r * LDC + c];
            v.x = to_tf32((v.x + bias[nbase + c]) * qscale);
            v.y = to_tf32((v.y + bias[nbase + c + 1]) * qscale);
            v.z = to_tf32((v.z + bias[nbase + c + 2]) * qscale);
            v.w = to_tf32((v.w + bias[nbase + c + 3]) * qscale);
            float* drow = dst + (((size_t)(b * NH + hh)) * T_SEQ + t) * DH;
            *(float4*)&drow[c] = v;
        }
    }
}

__global__ void __launch_bounds__(256) proj_gemm_kernel(
    const float* __restrict__ A, const float* __restrict__ W,
    const float* __restrict__ bias, float* __restrict__ out)
{
    const int K = DMODEL;
    const int tid = threadIdx.x, lane = tid & 31, wid = tid >> 5;
    const int bn = blockIdx.x, bm = blockIdx.y;
    const int wm = (wid & 3) * 32, wn = (wid >> 2) * 32;

    float acc[2][4][4];
#pragma unroll
    for (int mi = 0; mi < 2; mi++)
#pragma unroll
        for (int n8 = 0; n8 < 4; n8++)
#pragma unroll
            for (int c = 0; c < 4; c++) acc[mi][n8][c] = 0.f;

    gemm_core(A + (size_t)bm * 128 * K, W + (size_t)bn * 64 * K, K, acc, tid, wm, wn);

    float* Cs = g_smem;
    gemm_store_cs(acc, Cs, lane, wm, wn);
    __syncthreads();

    const int nbase = bn * 64;
#pragma unroll
    for (int it = 0; it < 8; it++) {
        int e = tid + it * 256;
        int r = e >> 4, c = (e & 15) << 2;
        int m = bm * 128 + r;
        float4 v = *(float4*)&Cs[r * LDC + c];
        v.x += bias[nbase + c];     v.y += bias[nbase + c + 1];
        v.z += bias[nbase + c + 2]; v.w += bias[nbase + c + 3];
        *(float4*)&out[(size_t)m * DMODEL + nbase + c] = v;
    }
}

// ---------------------------------------------------------------------------
// Flash attention: raw mma + ldmatrix + cp.async double-buffered K/V.
// 128 thr = 4 warps, 16 q-rows each. All operands pre-rounded tf32 in gmem;
// V pre-transposed so PV B-fragments are natural ldmatrix loads.
// ALD = 68: >= 64 data floats per row; 272B row stride keeps ldmatrix
// 16B-aligned and 8-row tiles bank-conflict-free (68 mod 32 = 4).
// ---------------------------------------------------------------------------
#define ALD 68
#define A_TILE (64 * ALD)   // floats
// layout: Qs | Ks0 | Ks1 | Vs0 | Vs1 | Ps
#define OFF_Q  0
#define OFF_K0 (A_TILE)
#define OFF_K1 (2 * A_TILE)
#define OFF_V0 (3 * A_TILE)
#define OFF_V1 (4 * A_TILE)
#define OFF_P  (5 * A_TILE)
#define ATTN_SMEM (6 * A_TILE * 4)   // 104448 B

__global__ void __launch_bounds__(128) attn_kernel(float* __restrict__ out)
{
    const int tid = threadIdx.x;
    const int warp = tid >> 5, lane = tid & 31;
    const int grp = lane >> 2, q4 = lane & 3;
    const int wm = warp * 16;
    const int qt = blockIdx.x, h = blockIdx.y, b = blockIdx.z;

    const size_t bh = ((size_t)(b * NH + h)) * T_SEQ * DH;
    const float* Qg = g_q + bh + (size_t)qt * 64 * DH;
    const float* Kg = g_k + bh;
    const float* Vtg = g_v + bh;   // [DH][T_SEQ]

    uint32_t smem_u = (uint32_t)__cvta_generic_to_shared(g_smem);
    const int r8 = tid >> 4, c8 = (tid & 15) << 2;   // staging row/col

    // fragment address bases (lane-dependent)
    const uint32_t a_pat = ((wm + (lane & 15)) * ALD + ((lane >> 4) << 2)) * 4;
    const uint32_t b_pat = ((((lane >> 4) << 3) + (lane & 7)) * ALD +
                            (((lane >> 3) & 1) << 2)) * 4;
    const uint32_t qa_base = smem_u + OFF_Q * 4 + a_pat;
    const uint32_t pa_base = smem_u + OFF_P * 4 + a_pat;

    // ---- prologue: stage Q + K/V tile 0 ----
#pragma unroll
    for (int it = 0; it < 8; it++) {
        int r = r8 + it * 8;
        CP16(smem_u + (OFF_Q + r * ALD + c8) * 4, Qg + r * DH + c8);
    }
#pragma unroll
    for (int it = 0; it < 8; it++) {
        int r = r8 + it * 8;
        CP16(smem_u + (OFF_K0 + r * ALD + c8) * 4, Kg + r * DH + c8);
        CP16(smem_u + (OFF_V0 + r * ALD + c8) * 4, Vtg + (size_t)r * T_SEQ + c8);
    }
    CP_COMMIT();

    float o[8][4];
#pragma unroll
    for (int j = 0; j < 8; j++)
#pragma unroll
        for (int c = 0; c < 4; c++) o[j][c] = 0.f;
    float m_lo = -1e30f, m_hi = -1e30f, l_lo = 0.f, l_hi = 0.f;

    int buf = 0;
#pragma unroll 1
    for (int ti = 0; ti < T_SEQ / 64; ti++) {
        CP_WAIT_ALL();
        __syncthreads();

        if (ti < T_SEQ / 64 - 1) {
            int kt = (ti + 1) * 64;
            int ko = (buf ^ 1) ? OFF_K1 : OFF_K0;
            int vo = (buf ^ 1) ? OFF_V1 : OFF_V0;
#pragma unroll
            for (int it = 0; it < 8; it++) {
                int r = r8 + it * 8;
                CP16(smem_u + (ko + r * ALD + c8) * 4, Kg + (size_t)(kt + r) * DH + c8);
                CP16(smem_u + (vo + r * ALD + c8) * 4, Vtg + (size_t)r * T_SEQ + kt + c8);
            }
            CP_COMMIT();
        }

        const uint32_t kb_base = smem_u + (buf ? OFF_K1 : OFF_K0) * 4 + b_pat;
        const uint32_t vb_base = smem_u + (buf ? OFF_V1 : OFF_V0) * 4 + b_pat;

        // ---- S = Q K^T ----
        float s[8][4];
#pragma unroll
        for (int j = 0; j < 8; j++)
#pragma unroll
            for (int c = 0; c < 4; c++) s[j][c] = 0.f;
#pragma unroll
        for (int kk = 0; kk < 8; kk++) {
            uint32_t aq[4];
            ldsm4(aq, qa_base + kk * 32);
#pragma unroll
            for (int np = 0; np < 4; np++) {
                uint32_t kb[4];
                ldsm4(kb, kb_base + np * 16 * ALD * 4 + kk * 32);
                mma8(s[np * 2], aq, kb[0], kb[1]);
                mma8(s[np * 2 + 1], aq, kb[2], kb[3]);
            }
        }

        // ---- online softmax ----
        float tm_lo = -1e30f, tm_hi = -1e30f;
#pragma unroll
        for (int j = 0; j < 8; j++) {
            tm_lo = fmaxf(tm_lo, fmaxf(s[j][0], s[j][1]));
            tm_hi = fmaxf(tm_hi, fmaxf(s[j][2], s[j][3]));
        }
        tm_lo = fmaxf(tm_lo, __shfl_xor_sync(0xffffffffu, tm_lo, 1));
        tm_lo = fmaxf(tm_lo, __shfl_xor_sync(0xffffffffu, tm_lo, 2));
        tm_hi = fmaxf(tm_hi, __shfl_xor_sync(0xffffffffu, tm_hi, 1));
        tm_hi = fmaxf(tm_hi, __shfl_xor_sync(0xffffffffu, tm_hi, 2));

        float mn_lo = fmaxf(m_lo, tm_lo), mn_hi = fmaxf(m_hi, tm_hi);
        float corr_lo = __expf(m_lo - mn_lo), corr_hi = __expf(m_hi - mn_hi);

        float rs_lo = 0.f, rs_hi = 0.f;
#pragma unroll
        for (int j = 0; j < 8; j++) {
            s[j][0] = __expf(s[j][0] - mn_lo);
            s[j][1] = __expf(s[j][1] - mn_lo);
            s[j][2] = __expf(s[j][2] - mn_hi);
            s[j][3] = __expf(s[j][3] - mn_hi);
            rs_lo += s[j][0] + s[j][1];
            rs_hi += s[j][2] + s[j][3];
        }
        rs_lo += __shfl_xor_sync(0xffffffffu, rs_lo, 1);
        rs_lo += __shfl_xor_sync(0xffffffffu, rs_lo, 2);
        rs_hi += __shfl_xor_sync(0xffffffffu, rs_hi, 1);
        rs_hi += __shfl_xor_sync(0xffffffffu, rs_hi, 2);

        l_lo = l_lo * corr_lo + rs_lo;  m_lo = mn_lo;
        l_hi = l_hi * corr_hi + rs_hi;  m_hi = mn_hi;
#pragma unroll
        for (int j = 0; j < 8; j++) {
            o[j][0] *= corr_lo; o[j][1] *= corr_lo;
            o[j][2] *= corr_hi; o[j][3] *= corr_hi;
        }

        // ---- P -> smem (tf32) for A-fragment reload ----
        float* Ps = g_smem + OFF_P;
#pragma unroll
        for (int j = 0; j < 8; j++) {
            *(float2*)&Ps[(wm + grp) * ALD + j * 8 + 2 * q4] =
                make_float2(to_tf32(s[j][0]), to_tf32(s[j][1]));
            *(float2*)&Ps[(wm + grp + 8) * ALD + j * 8 + 2 * q4] =
                make_float2(to_tf32(s[j][2]), to_tf32(s[j][3]));
        }
        __syncwarp();

        // ---- O += P V  (V transposed: natural ldmatrix B-fragments) ----
#pragma unroll
        for (int kk = 0; kk < 8; kk++) {
            uint32_t ap[4];
            ldsm4(ap, pa_base + kk * 32);
#pragma unroll
            for (int np = 0; np < 4; np++) {
                uint32_t vb[4];
                ldsm4(vb, vb_base + np * 16 * ALD * 4 + kk * 32);
                mma8(o[np * 2], ap, vb[0], vb[1]);
                mma8(o[np * 2 + 1], ap, vb[2], vb[3]);
            }
        }
        __syncwarp();
        buf ^= 1;
    }

    // ---- normalize + write [B,T,H*Dh] ----
    float inv_lo = 1.f / l_lo, inv_hi = 1.f / l_hi;
    int t_lo = qt * 64 + wm + grp;
    float* row_lo = out + ((size_t)b * T_SEQ + t_lo) * DMODEL + h * DH;
    float* row_hi = row_lo + 8 * DMODEL;
#pragma unroll
    for (int j = 0; j < 8; j++) {
        *(float2*)&row_lo[j * 8 + 2 * q4] =
            make_float2(o[j][0] * inv_lo, o[j][1] * inv_lo);
        *(float2*)&row_hi[j * 8 + 2 * q4] =
            make_float2(o[j][2] * inv_hi, o[j][3] * inv_hi);
    }
}

// ---------------------------------------------------------------------------
extern "C" void kernel_launch(void* const* d_in, const int* in_sizes, int n_in,
                              void* d_out, int out_size)
{
    const float* x      = (const float*)d_in[0];
    const float* W_qkv  = (const float*)d_in[1];
    const float* b_qkv  = (const float*)d_in[2];
    const float* W_proj = (const float*)d_in[3];
    const float* b_proj = (const float*)d_in[4];
    float* out = (float*)d_out;

    cudaFuncSetAttribute(qkv_gemm_kernel,
                         cudaFuncAttributeMaxDynamicSharedMemorySize, GEMM_SMEM);
    cudaFuncSetAttribute(proj_gemm_kernel,
                         cudaFuncAttributeMaxDynamicSharedMemorySize, GEMM_SMEM);
    cudaFuncSetAttribute(attn_kernel,
                         cudaFuncAttributeMaxDynamicSharedMemorySize, ATTN_SMEM);

    float* attn_scratch;
    cudaGetSymbolAddress((void**)&attn_scratch, g_attn);

    {
        dim3 grid(3 * DMODEL / 64, (NB * T_SEQ) / 128);  // (36, 64)
        qkv_gemm_kernel<<<grid, 256, GEMM_SMEM>>>(x, W_qkv, b_qkv);
    }
    {
        dim3 grid(T_SEQ / 64, NH, NB);  // (32, 12, 4)
        attn_kernel<<<grid, 128, ATTN_SMEM>>>(attn_scratch);
    }
    {
        dim3 grid(DMODEL / 64, (NB * T_SEQ) / 128);  // (12, 64)
        proj_gemm_kernel<<<grid, 256, GEMM_SMEM>>>(attn_scratch, W_proj, b_proj, out);
    }
}